// round 16
// baseline (speedup 1.0000x reference)
#include <cuda_runtime.h>
#include <cuda_fp16.h>
#include <cstdint>

#define NIN 7
#define H   32
#define TPB 128
#define ITERS 4          // 128 samples per CTA per iter

typedef unsigned long long u64;
typedef unsigned int u32;

// ---------------- constant weight image --------------------------------------
//  floats: b0 @1248, b1 @1280, w2 @1312, b2 @1344
__constant__ float4 CW4[337];
__device__ float DSTG[1348];
// Layer-1 B fragments (m16n8k16 fp16, PTX layout): t = kt*4 + nt, t in [0,8)
__device__ uint2 BFG[256];
// Layer-0 B fragments: t = nt in [0,4), B = [W0 | W0] fp16
__device__ uint2 BFG0[128];

__device__ __forceinline__ float cwf(int fidx) { return ((const float*)CW4)[fidx]; }

// ---------------- scalar helpers ----------------
__device__ __forceinline__ u64 pk2(float a, float b) {
    u64 r; asm("mov.b64 %0, {%1, %2};" : "=l"(r) : "f"(a), "f"(b)); return r;
}
__device__ __forceinline__ float2 upk2(u64 v) {
    float2 f; asm("mov.b64 {%0, %1}, %2;" : "=f"(f.x), "=f"(f.y) : "l"(v)); return f;
}
__device__ __forceinline__ u64 ffma2(u64 a, u64 b, u64 c) {
    u64 r; asm("fma.rn.f32x2 %0, %1, %2, %3;" : "=l"(r) : "l"(a), "l"(b), "l"(c)); return r;
}
__device__ __forceinline__ float tanh_approx(float x) {
    float r; asm("tanh.approx.f32 %0, %1;" : "=f"(r) : "f"(x)); return r;
}
// packed fp16x2 tanh: ONE MUFU for two values (sm_75+)
__device__ __forceinline__ u32 tanh_h2(u32 a) {
    u32 r; asm("tanh.approx.f16x2 %0, %1;" : "=r"(r) : "r"(a)); return r;
}
// lower 16 bits = fp16(a), upper = fp16(b)
__device__ __forceinline__ u32 f16x2_of(float a, float b) {
    u32 r; asm("cvt.rn.f16x2.f32 %0, %1, %2;" : "=r"(r) : "f"(b), "f"(a)); return r;
}
__device__ __forceinline__ float2 unpk_h2(u32 v) {
    __half2 h = *reinterpret_cast<__half2*>(&v);
    return make_float2(__low2float(h), __high2float(h));
}
__device__ __forceinline__ u32 smem_u32(const void* p) {
    u32 a; asm("{ .reg .u64 t; cvta.to.shared.u64 t, %1; cvt.u32.u64 %0, t; }"
               : "=r"(a) : "l"(p));
    return a;
}
__device__ __forceinline__ float2 lds2(u32 addr) {
    float2 v;
    asm volatile("ld.shared.v2.f32 {%0,%1}, [%2];" : "=f"(v.x), "=f"(v.y) : "r"(addr));
    return v;
}
__device__ __forceinline__ void ldsm4(u32* r, u32 addr) {
    asm volatile("ldmatrix.sync.aligned.m8n8.x4.shared.b16 {%0,%1,%2,%3}, [%4];"
                 : "=r"(r[0]), "=r"(r[1]), "=r"(r[2]), "=r"(r[3]) : "r"(addr));
}
__device__ __forceinline__ void mma_f16(float* d, const u32* a, uint2 b) {
    asm volatile(
        "mma.sync.aligned.m16n8k16.row.col.f32.f16.f16.f32 "
        "{%0,%1,%2,%3}, {%4,%5,%6,%7}, {%8,%9}, {%0,%1,%2,%3};"
        : "+f"(d[0]), "+f"(d[1]), "+f"(d[2]), "+f"(d[3])
        : "r"(a[0]), "r"(a[1]), "r"(a[2]), "r"(a[3]), "r"(b.x), "r"(b.y));
}

// ---------------- prep kernel ----------------
__global__ void prep_kernel(const float* __restrict__ w0, const float* __restrict__ b0,
                            const float* __restrict__ w1, const float* __restrict__ b1,
                            const float* __restrict__ w2, const float* __restrict__ b2)
{
    int g = blockIdx.x * blockDim.x + threadIdx.x;
    int stride = gridDim.x * blockDim.x;

    for (int k = g; k < 1348; k += stride) {
        if (k < 224) {
            int i = k >> 5, h = k & 31;
            DSTG[k] = w0[h * NIN + i];
        } else if (k < 1248) {
            int kk = k - 224;
            int i = kk >> 5, h = kk & 31;
            DSTG[k] = w1[h * H + i];
        } else if (k < 1280) DSTG[k] = b0[k - 1248];
        else if (k < 1312)   DSTG[k] = b1[k - 1280];
        else if (k < 1344)   DSTG[k] = w2[k - 1312];
        else                 DSTG[k] = b2[0];
    }

    // Layer-1 B frags (fp16): B[k][n] = w1[n][k]; t = kt*4 + nt
    //   n = 8nt + lane/4, k0 = 16kt + 2*(lane%4)
    for (int idx = g; idx < 256; idx += stride) {
        int t = idx >> 5, l = idx & 31;
        int kt = t >> 2, nt = t & 3;
        int n = 8 * nt + (l >> 2);
        int k0 = 16 * kt + 2 * (l & 3);
        int ks[4] = { k0, k0 + 1, k0 + 8, k0 + 9 };
        u32 p[4];
        for (int j = 0; j < 4; ++j) {
            union { __half h; unsigned short s; } c;
            c.h = __float2half_rn(w1[n * H + ks[j]]);
            p[j] = c.s;
        }
        BFG[idx] = make_uint2(p[0] | (p[1] << 16), p[2] | (p[3] << 16));
    }

    // Layer-0 B frags (fp16, K=16): B = [W0 | W0] (k%8 < 7 real, col 7 zero)
    for (int idx = g; idx < 128; idx += stride) {
        int t = idx >> 5, l = idx & 31;
        int nt = t & 3;
        int n = 8 * nt + (l >> 2);
        int k0 = 2 * (l & 3);
        int ks[4] = { k0, k0 + 1, k0 + 8, k0 + 9 };
        u32 p[4];
        for (int j = 0; j < 4; ++j) {
            int i = ks[j] & 7;
            float val = (i < NIN) ? w0[n * NIN + i] : 0.0f;
            union { __half h; unsigned short s; } c;
            c.h = __float2half_rn(val);
            p[j] = c.s;
        }
        BFG0[idx] = make_uint2(p[0] | (p[1] << 16), p[2] | (p[3] << 16));
    }
}

// ---------------- main kernel ----------------
__global__ __launch_bounds__(TPB, 6)
void WarpTileMLP_kernel(const float* __restrict__ q, float* __restrict__ out)
{
    // per-warp input staging: 32 rows x 32B ([x_hi(7),pad | x_lo(7),pad] fp16)
    __shared__ __align__(16) char zstage[4][1024];
    // bias/weight tables for fragment-layout epilogues (broadcast LDS)
    __shared__ __align__(8) float ctab[96];   // [0,32) b0, [32,64) b1, [64,96) w2

    const int tid  = threadIdx.x;
    const int wid  = tid >> 5;
    const int lane = tid & 31;

    if (tid < 96) {
        int v = tid >> 5, e = tid & 31;          // v: 0=b0, 1=b1, 2=w2
        ctab[tid] = cwf(1248 + v * 32 + e);
    }
    __syncthreads();

    const u32 sbeg = smem_u32(&zstage[wid][0]);
    // per-lane byte offset within a pair-table row: cols 2*(lane&3), +1
    const u32 ctb = smem_u32(ctab) + (u32)((lane & 3) * 8);

    // STS offsets: row = lane, logical chunk c at phys (c ^ ((row>>2)&1))
    const u32 sts0 = (u32)lane * 32u + (u32)(((0 ^ ((lane >> 2) & 1))) * 16);
    const u32 sts1 = (u32)lane * 32u + (u32)(((1 ^ ((lane >> 2) & 1))) * 16);

    // ldmatrix A0 offsets: row = 16mt + r16, logical chunk cb = lane>>4
    u32 lds0[2];
    {
        int r16 = lane & 15, cb = lane >> 4;
#pragma unroll
        for (int mt = 0; mt < 2; ++mt)
            lds0[mt] = (u32)((16 * mt + r16) * 32 +
                             ((cb ^ ((r16 >> 2) & 1)) * 16));
    }

    const float b2v = cwf(1344);

    // prefetch iter-0 inputs
    float x[NIN];
    {
        const float* qr = q + (((long)blockIdx.x * ITERS) * TPB + wid * 32 + lane) * NIN;
#pragma unroll
        for (int i = 0; i < NIN; ++i) x[i] = __ldg(qr + i);
    }

    for (int it = 0; it < ITERS; ++it) {
        const long sbase = (((long)blockIdx.x * ITERS + it) * TPB) + wid * 32;

        // ---- split x into fp16 hi/lo and stage one 32B row ----
        u32 xh[4], xl[4];
        {
            float xs[8];
#pragma unroll
            for (int i = 0; i < NIN; ++i) xs[i] = x[i];
            xs[7] = 0.0f;
#pragma unroll
            for (int p = 0; p < 4; ++p) {
                u32 hp = f16x2_of(xs[2 * p], xs[2 * p + 1]);
                float2 hv = unpk_h2(hp);
                xh[p] = hp;
                xl[p] = f16x2_of(xs[2 * p] - hv.x, xs[2 * p + 1] - hv.y);
            }
        }
        asm volatile("st.shared.v4.b32 [%0], {%1,%2,%3,%4};" ::
            "r"(sbeg + sts0), "r"(xh[0]), "r"(xh[1]), "r"(xh[2]), "r"(xh[3]) : "memory");
        asm volatile("st.shared.v4.b32 [%0], {%1,%2,%3,%4};" ::
            "r"(sbeg + sts1), "r"(xl[0]), "r"(xl[1]), "r"(xl[2]), "r"(xl[3]) : "memory");
        __syncwarp();

        // ---- prefetch next iter's inputs (x is dead now) ----
        if (it + 1 < ITERS) {
            const float* qn = q + (sbase + TPB + lane) * NIN;
#pragma unroll
            for (int i = 0; i < NIN; ++i) x[i] = __ldg(qn + i);
        }

        // ---- A0 fragments ----
        u32 A0[2][4];
        ldsm4(A0[0], sbeg + lds0[0]);
        ldsm4(A0[1], sbeg + lds0[1]);
        __syncwarp();

        // ---- layer 0 MMA + bias + packed f16x2 tanh -> layer-1 A fragments --
        // A0 = [x_hi | x_lo], B0 = [W0 | W0]: one MMA computes x@W0 (x exact).
        // tanh done on fp16x2 (1 MUFU / 2 values); result IS the A-fragment.
        u32 AH[2][2][4];
#pragma unroll
        for (int kt = 0; kt < 2; ++kt) {
            uint2 b0f0 = BFG0[(2 * kt) * 32 + lane];       // nt = 2kt
            uint2 b0f1 = BFG0[(2 * kt + 1) * 32 + lane];   // nt = 2kt+1
            float2 pb0a = lds2(ctb + (2 * kt) * 32);
            float2 pb0b = lds2(ctb + (2 * kt + 1) * 32);
#pragma unroll
            for (int mt = 0; mt < 2; ++mt) {
                float d0[4] = {0.f, 0.f, 0.f, 0.f};
                float d1[4] = {0.f, 0.f, 0.f, 0.f};
                mma_f16(d0, A0[mt], b0f0);    // x @ W0 (tile nt=2kt)
                mma_f16(d1, A0[mt], b0f1);    // x @ W0 (tile nt=2kt+1)

                AH[mt][kt][0] = tanh_h2(f16x2_of(d0[0] + pb0a.x, d0[1] + pb0a.y));
                AH[mt][kt][1] = tanh_h2(f16x2_of(d0[2] + pb0a.x, d0[3] + pb0a.y));
                AH[mt][kt][2] = tanh_h2(f16x2_of(d1[0] + pb0b.x, d1[1] + pb0b.y));
                AH[mt][kt][3] = tanh_h2(f16x2_of(d1[2] + pb0b.x, d1[3] + pb0b.y));
            }
        }

        // ---- layer 1 MMA (2 per tile: Z @ [W k0,k1]) + fused layer 2 -------
        u64 rs2[4];
#pragma unroll
        for (int j = 0; j < 4; ++j) rs2[j] = pk2(0.0f, 0.0f);

#pragma unroll
        for (int nt = 0; nt < 4; ++nt) {
            uint2 bw0 = BFG[(0 + nt) * 32 + lane];     // W, k-tile 0
            uint2 bw1 = BFG[(4 + nt) * 32 + lane];     // W, k-tile 1
            float2 pb1 = lds2(ctb + 128 + nt * 32);    // b1 pair
            float2 pw2 = lds2(ctb + 256 + nt * 32);    // w2 pair
            u64 wpk = pk2(pw2.x, pw2.y);
#pragma unroll
            for (int mt = 0; mt < 2; ++mt) {
                float d[4] = {0.0f, 0.0f, 0.0f, 0.0f};
                mma_f16(d, AH[mt][0], bw0);       // Z @ W (k0)
                mma_f16(d, AH[mt][1], bw1);       // Z @ W (k1)

                float t0 = tanh_approx(d[0] + pb1.x);
                float t1 = tanh_approx(d[1] + pb1.y);
                rs2[2 * mt] = ffma2(wpk, pk2(t0, t1), rs2[2 * mt]);
                float t2 = tanh_approx(d[2] + pb1.x);
                float t3 = tanh_approx(d[3] + pb1.y);
                rs2[2 * mt + 1] = ffma2(wpk, pk2(t2, t3), rs2[2 * mt + 1]);
            }
        }

        // ---- quad reduce + store ----
        float rs[4];
#pragma unroll
        for (int j = 0; j < 4; ++j) {
            float2 p = upk2(rs2[j]);
            float v = p.x + p.y;
            v += __shfl_xor_sync(0xffffffffu, v, 1);
            v += __shfl_xor_sync(0xffffffffu, v, 2);
            rs[j] = v;
        }
        const int row = (lane >> 2) + 8 * (lane & 3);
        out[sbase + row] = rs[lane & 3] + b2v;
        __syncwarp();   // staging reuse: all ldsm done before next iter's STS
    }
}

extern "C" void kernel_launch(void* const* d_in, const int* in_sizes, int n_in,
                              void* d_out, int out_size)
{
    const float* q  = (const float*)d_in[0];
    const float* w0 = (const float*)d_in[1];
    const float* b0 = (const float*)d_in[2];
    const float* w1 = (const float*)d_in[3];
    const float* b1 = (const float*)d_in[4];
    const float* w2 = (const float*)d_in[5];
    const float* b2 = (const float*)d_in[6];
    float* out = (float*)d_out;

    prep_kernel<<<17, TPB>>>(w0, b0, w1, b1, w2, b2);

    void* sym = nullptr; void* stg = nullptr;
    cudaGetSymbolAddress(&sym, CW4);
    cudaGetSymbolAddress(&stg, DSTG);
    cudaMemcpyAsync(sym, stg, 1348 * sizeof(float), cudaMemcpyDeviceToDevice);

    const int B = in_sizes[0] / NIN;                 // 2097152
    const int blocks = B / (TPB * ITERS);            // 4096
    WarpTileMLP_kernel<<<blocks, TPB>>>(q, out);
}

// round 17
// speedup vs baseline: 1.0960x; 1.0960x over previous
#include <cuda_runtime.h>
#include <cuda_fp16.h>
#include <cstdint>

#define NIN 7
#define H   32
#define TPB 128
#define ITERS 4          // 128 samples per CTA per iter

typedef unsigned long long u64;
typedef unsigned int u32;

// Layer-1 B fragments (m16n8k16 fp16, PTX layout): t = kt*4 + nt, t in [0,8)
__device__ uint2 BFG[256];
// Layer-0 B fragments: t = nt in [0,4), B = [W0 | W0] fp16
__device__ uint2 BFG0[128];

// ---------------- scalar helpers ----------------
__device__ __forceinline__ u64 pk2(float a, float b) {
    u64 r; asm("mov.b64 %0, {%1, %2};" : "=l"(r) : "f"(a), "f"(b)); return r;
}
__device__ __forceinline__ float2 upk2(u64 v) {
    float2 f; asm("mov.b64 {%0, %1}, %2;" : "=f"(f.x), "=f"(f.y) : "l"(v)); return f;
}
__device__ __forceinline__ u64 ffma2(u64 a, u64 b, u64 c) {
    u64 r; asm("fma.rn.f32x2 %0, %1, %2, %3;" : "=l"(r) : "l"(a), "l"(b), "l"(c)); return r;
}
__device__ __forceinline__ float tanh_approx(float x) {
    float r; asm("tanh.approx.f32 %0, %1;" : "=f"(r) : "f"(x)); return r;
}
// lower 16 bits = fp16(a), upper = fp16(b)
__device__ __forceinline__ u32 f16x2_of(float a, float b) {
    u32 r; asm("cvt.rn.f16x2.f32 %0, %1, %2;" : "=r"(r) : "f"(b), "f"(a)); return r;
}
__device__ __forceinline__ float2 unpk_h2(u32 v) {
    __half2 h = *reinterpret_cast<__half2*>(&v);
    return make_float2(__low2float(h), __high2float(h));
}
__device__ __forceinline__ u32 smem_u32(const void* p) {
    u32 a; asm("{ .reg .u64 t; cvta.to.shared.u64 t, %1; cvt.u32.u64 %0, t; }"
               : "=r"(a) : "l"(p));
    return a;
}
__device__ __forceinline__ float2 lds2(u32 addr) {
    float2 v;
    asm volatile("ld.shared.v2.f32 {%0,%1}, [%2];" : "=f"(v.x), "=f"(v.y) : "r"(addr));
    return v;
}
__device__ __forceinline__ void ldsm4(u32* r, u32 addr) {
    asm volatile("ldmatrix.sync.aligned.m8n8.x4.shared.b16 {%0,%1,%2,%3}, [%4];"
                 : "=r"(r[0]), "=r"(r[1]), "=r"(r[2]), "=r"(r[3]) : "r"(addr));
}
__device__ __forceinline__ void mma_f16(float* d, const u32* a, uint2 b) {
    asm volatile(
        "mma.sync.aligned.m16n8k16.row.col.f32.f16.f16.f32 "
        "{%0,%1,%2,%3}, {%4,%5,%6,%7}, {%8,%9}, {%0,%1,%2,%3};"
        : "+f"(d[0]), "+f"(d[1]), "+f"(d[2]), "+f"(d[3])
        : "r"(a[0]), "r"(a[1]), "r"(a[2]), "r"(a[3]), "r"(b.x), "r"(b.y));
}

// ---------------- prep kernel: build MMA B fragments only ----------------
__global__ void prep_kernel(const float* __restrict__ w0, const float* __restrict__ w1)
{
    int g = blockIdx.x * blockDim.x + threadIdx.x;
    int stride = gridDim.x * blockDim.x;

    // Layer-1 B frags (fp16): B[k][n] = w1[n][k]; t = kt*4 + nt
    //   n = 8nt + lane/4, k0 = 16kt + 2*(lane%4)
    for (int idx = g; idx < 256; idx += stride) {
        int t = idx >> 5, l = idx & 31;
        int kt = t >> 2, nt = t & 3;
        int n = 8 * nt + (l >> 2);
        int k0 = 16 * kt + 2 * (l & 3);
        int ks[4] = { k0, k0 + 1, k0 + 8, k0 + 9 };
        u32 p[4];
        for (int j = 0; j < 4; ++j) {
            union { __half h; unsigned short s; } c;
            c.h = __float2half_rn(w1[n * H + ks[j]]);
            p[j] = c.s;
        }
        BFG[idx] = make_uint2(p[0] | (p[1] << 16), p[2] | (p[3] << 16));
    }

    // Layer-0 B frags (fp16, K=16): B = [W0 | W0] (k%8 < 7 real, col 7 zero)
    for (int idx = g; idx < 128; idx += stride) {
        int t = idx >> 5, l = idx & 31;
        int nt = t & 3;
        int n = 8 * nt + (l >> 2);
        int k0 = 2 * (l & 3);
        int ks[4] = { k0, k0 + 1, k0 + 8, k0 + 9 };
        u32 p[4];
        for (int j = 0; j < 4; ++j) {
            int i = ks[j] & 7;
            float val = (i < NIN) ? w0[n * NIN + i] : 0.0f;
            union { __half h; unsigned short s; } c;
            c.h = __float2half_rn(val);
            p[j] = c.s;
        }
        BFG0[idx] = make_uint2(p[0] | (p[1] << 16), p[2] | (p[3] << 16));
    }
}

// ---------------- main kernel ----------------
__global__ __launch_bounds__(TPB, 5)
void WarpTileMLP_kernel(const float* __restrict__ q,
                        const float* __restrict__ b0g, const float* __restrict__ b1g,
                        const float* __restrict__ w2g, const float* __restrict__ b2g,
                        float* __restrict__ out)
{
    // per-warp input staging: 32 rows x 32B ([x_hi(7),pad | x_lo(7),pad] fp16)
    __shared__ __align__(16) char zstage[4][1024];
    // bias/weight tables for fragment-layout epilogues (broadcast LDS)
    __shared__ __align__(8) float ctab[100];  // [0,32) b0, [32,64) b1, [64,96) w2, [96] b2

    const int tid  = threadIdx.x;
    const int wid  = tid >> 5;
    const int lane = tid & 31;

    if (tid < 96) {
        int v = tid >> 5, e = tid & 31;          // v: 0=b0, 1=b1, 2=w2
        ctab[tid] = (v == 0) ? b0g[e] : (v == 1) ? b1g[e] : w2g[e];
    }
    if (tid == 96) ctab[96] = b2g[0];
    __syncthreads();

    const u32 sbeg = smem_u32(&zstage[wid][0]);
    // per-lane byte offset within a pair-table row: cols 2*(lane&3), +1
    const u32 ctb = smem_u32(ctab) + (u32)((lane & 3) * 8);

    // STS offsets: row = lane, logical chunk c at phys (c ^ ((row>>2)&1))
    const u32 sts0 = (u32)lane * 32u + (u32)(((0 ^ ((lane >> 2) & 1))) * 16);
    const u32 sts1 = (u32)lane * 32u + (u32)(((1 ^ ((lane >> 2) & 1))) * 16);

    // ldmatrix A0 offsets: row = 16mt + r16, logical chunk cb = lane>>4
    u32 lds0[2];
    {
        int r16 = lane & 15, cb = lane >> 4;
#pragma unroll
        for (int mt = 0; mt < 2; ++mt)
            lds0[mt] = (u32)((16 * mt + r16) * 32 +
                             ((cb ^ ((r16 >> 2) & 1)) * 16));
    }

    // ---- hoist loop-invariant B fragments into registers (12 x uint2) ----
    uint2 b0f[4], bw[8];
#pragma unroll
    for (int t = 0; t < 4; ++t) b0f[t] = BFG0[t * 32 + lane];
#pragma unroll
    for (int t = 0; t < 8; ++t) bw[t] = BFG[t * 32 + lane];

    // prefetch iter-0 inputs
    float x[NIN];
    {
        const float* qr = q + (((long)blockIdx.x * ITERS) * TPB + wid * 32 + lane) * NIN;
#pragma unroll
        for (int i = 0; i < NIN; ++i) x[i] = __ldg(qr + i);
    }

    for (int it = 0; it < ITERS; ++it) {
        const long sbase = (((long)blockIdx.x * ITERS + it) * TPB) + wid * 32;

        // ---- split x into fp16 hi/lo and stage one 32B row ----
        u32 xh[4], xl[4];
        {
            float xs[8];
#pragma unroll
            for (int i = 0; i < NIN; ++i) xs[i] = x[i];
            xs[7] = 0.0f;
#pragma unroll
            for (int p = 0; p < 4; ++p) {
                u32 hp = f16x2_of(xs[2 * p], xs[2 * p + 1]);
                float2 hv = unpk_h2(hp);
                xh[p] = hp;
                xl[p] = f16x2_of(xs[2 * p] - hv.x, xs[2 * p + 1] - hv.y);
            }
        }
        asm volatile("st.shared.v4.b32 [%0], {%1,%2,%3,%4};" ::
            "r"(sbeg + sts0), "r"(xh[0]), "r"(xh[1]), "r"(xh[2]), "r"(xh[3]) : "memory");
        asm volatile("st.shared.v4.b32 [%0], {%1,%2,%3,%4};" ::
            "r"(sbeg + sts1), "r"(xl[0]), "r"(xl[1]), "r"(xl[2]), "r"(xl[3]) : "memory");
        __syncwarp();

        // ---- prefetch next iter's inputs (x is dead now) ----
        if (it + 1 < ITERS) {
            const float* qn = q + (sbase + TPB + lane) * NIN;
#pragma unroll
            for (int i = 0; i < NIN; ++i) x[i] = __ldg(qn + i);
        }

        // ---- A0 fragments ----
        u32 A0[2][4];
        ldsm4(A0[0], sbeg + lds0[0]);
        ldsm4(A0[1], sbeg + lds0[1]);
        __syncwarp();

        // ---- layer 0 MMA + bias + tanh -> fp16 layer-1 A fragments ---------
        // A0 = [x_hi | x_lo], B0 = [W0 | W0]: one MMA computes x@W0 (x exact).
        u32 AH[2][2][4];
#pragma unroll
        for (int kt = 0; kt < 2; ++kt) {
            float2 pb0a = lds2(ctb + (2 * kt) * 32);
            float2 pb0b = lds2(ctb + (2 * kt + 1) * 32);
#pragma unroll
            for (int mt = 0; mt < 2; ++mt) {
                float d0[4] = {0.f, 0.f, 0.f, 0.f};
                float d1[4] = {0.f, 0.f, 0.f, 0.f};
                mma_f16(d0, A0[mt], b0f[2 * kt]);       // x @ W0 (tile nt=2kt)
                mma_f16(d1, A0[mt], b0f[2 * kt + 1]);   // x @ W0 (tile nt=2kt+1)

                AH[mt][kt][0] = f16x2_of(tanh_approx(d0[0] + pb0a.x),
                                         tanh_approx(d0[1] + pb0a.y));
                AH[mt][kt][1] = f16x2_of(tanh_approx(d0[2] + pb0a.x),
                                         tanh_approx(d0[3] + pb0a.y));
                AH[mt][kt][2] = f16x2_of(tanh_approx(d1[0] + pb0b.x),
                                         tanh_approx(d1[1] + pb0b.y));
                AH[mt][kt][3] = f16x2_of(tanh_approx(d1[2] + pb0b.x),
                                         tanh_approx(d1[3] + pb0b.y));
            }
        }

        // ---- layer 1 MMA (2 per tile: Z @ [W k0,k1]) + fused layer 2 -------
        u64 rs2[4];
#pragma unroll
        for (int j = 0; j < 4; ++j) rs2[j] = pk2(0.0f, 0.0f);

#pragma unroll
        for (int nt = 0; nt < 4; ++nt) {
            float2 pb1 = lds2(ctb + 128 + nt * 32);    // b1 pair
            float2 pw2 = lds2(ctb + 256 + nt * 32);    // w2 pair
            u64 wpk = pk2(pw2.x, pw2.y);
#pragma unroll
            for (int mt = 0; mt < 2; ++mt) {
                float d[4] = {0.0f, 0.0f, 0.0f, 0.0f};
                mma_f16(d, AH[mt][0], bw[nt]);        // Z @ W (k0)
                mma_f16(d, AH[mt][1], bw[4 + nt]);    // Z @ W (k1)

                float t0 = tanh_approx(d[0] + pb1.x);
                float t1 = tanh_approx(d[1] + pb1.y);
                rs2[2 * mt] = ffma2(wpk, pk2(t0, t1), rs2[2 * mt]);
                float t2 = tanh_approx(d[2] + pb1.x);
                float t3 = tanh_approx(d[3] + pb1.y);
                rs2[2 * mt + 1] = ffma2(wpk, pk2(t2, t3), rs2[2 * mt + 1]);
            }
        }

        // ---- quad reduce + store ----
        float rs[4];
#pragma unroll
        for (int j = 0; j < 4; ++j) {
            float2 p = upk2(rs2[j]);
            float v = p.x + p.y;
            v += __shfl_xor_sync(0xffffffffu, v, 1);
            v += __shfl_xor_sync(0xffffffffu, v, 2);
            rs[j] = v;
        }
        const int row = (lane >> 2) + 8 * (lane & 3);
        out[sbase + row] = rs[lane & 3] + ctab[96];
        __syncwarp();   // staging reuse: all ldsm done before next iter's STS
    }
}

extern "C" void kernel_launch(void* const* d_in, const int* in_sizes, int n_in,
                              void* d_out, int out_size)
{
    const float* q  = (const float*)d_in[0];
    const float* w0 = (const float*)d_in[1];
    const float* b0 = (const float*)d_in[2];
    const float* w1 = (const float*)d_in[3];
    const float* b1 = (const float*)d_in[4];
    const float* w2 = (const float*)d_in[5];
    const float* b2 = (const float*)d_in[6];
    float* out = (float*)d_out;

    prep_kernel<<<6, TPB>>>(w0, w1);

    const int B = in_sizes[0] / NIN;                 // 2097152
    const int blocks = B / (TPB * ITERS);            // 4096
    WarpTileMLP_kernel<<<blocks, TPB>>>(q, b0, b1, w2, b2, out);
}